// round 15
// baseline (speedup 1.0000x reference)
#include <cuda_runtime.h>
#include <cuda_bf16.h>
#include <cstdint>

// ProcessorNet, fully tensor-core resident, single kernel:
//   z_0 = x@wd.T + bd            (MMA: x hi/lo via float4 LDG, permuted k)
//   m_t = relu(z_t + t*c)*prog_t ; R += m_t (I-MMA) ; z += m_t@A (MMA, A-hi)
//   out = x + R@wu.T + 64*bu     (MMA: R hi/lo, permuted n -> float4 LDG/STG)
// All consts computed per-block into smem (no setup kernel, no __device__ glob).
// k-permutation (phase A): frag k-pos {2tg,2tg+1,2tg+8,2tg+9} <-> global k
//   kc*16 + {4tg,4tg+1,4tg+2,4tg+3}  (wd fragments built to match)
// n-permutation (phase C): frag (grp,c) -> global h = s*16 + 2c + grp
//   so lane's 4 outputs are h = s*16 + 4tg + {0..3}  (wu frags + bu matched)

#define HDIM 128
#define LSTEPS 64

typedef unsigned long long u64;

struct alignas(16) SC {
    float A[16][16];            // A[j][i] = (wu.T@wd.T)[j][i]
    float prog[LSTEPS][16];
    float bd[16];
    float c[16];                // bu @ wd.T
    float bu64[128];            // 64*bu
    u64 wdf[8][2][2][32];       // [kc][cf][hi/lo][lane] wd B-frags (perm k)
    u64 wuf[8][2][2][32];       // [s][grp][hi/lo][lane]  wu B-frags (perm n)
};

__device__ __forceinline__ float bhi_f(float v) {
    return __bfloat162float(__float2bfloat16(v));
}
__device__ __forceinline__ uint32_t pkbf(float a, float b) {   // low=a, high=b
    __nv_bfloat162 h = __floats2bfloat162_rn(a, b);
    return *reinterpret_cast<uint32_t*>(&h);
}
__device__ __forceinline__ u64 mk_bfrag(float v0, float v1, float v2, float v3,
                                        int hl) {
    if (hl) {
        v0 -= bhi_f(v0); v1 -= bhi_f(v1);
        v2 -= bhi_f(v2); v3 -= bhi_f(v3);
    }
    return ((u64)pkbf(v2, v3) << 32) | pkbf(v0, v1);
}
__device__ __forceinline__ void split_u64(u64 v, uint32_t* b) {
    b[0] = (uint32_t)v; b[1] = (uint32_t)(v >> 32);
}
__device__ __forceinline__ void mma_bf16(float* d, const uint32_t* a,
                                         const uint32_t* b) {
    asm volatile(
        "mma.sync.aligned.m16n8k16.row.col.f32.bf16.bf16.f32 "
        "{%0,%1,%2,%3}, {%4,%5,%6,%7}, {%8,%9}, {%0,%1,%2,%3};\n"
        : "+f"(d[0]), "+f"(d[1]), "+f"(d[2]), "+f"(d[3])
        : "r"(a[0]), "r"(a[1]), "r"(a[2]), "r"(a[3]), "r"(b[0]), "r"(b[1]));
}

__global__ __launch_bounds__(256, 4)
void proc_kernel(const float* __restrict__ x, float* __restrict__ out,
                 const float* __restrict__ prog, const float* __restrict__ wd,
                 const float* __restrict__ bd, const float* __restrict__ wu,
                 const float* __restrict__ bu) {
    __shared__ SC sc;
    int tid = threadIdx.x;

    // ---- per-block const setup (parallel, redundant across blocks) ----
    {   // A[j][i] = sum_h wu[h][j] * wd[i][h]
        int j = tid >> 4, i = tid & 15;
        float s = 0.f;
        #pragma unroll 8
        for (int h = 0; h < HDIM; ++h) s += wu[h * 16 + j] * wd[i * HDIM + h];
        sc.A[j][i] = s;
    }
    if (tid < 16) {
        int i = tid;
        float s = 0.f;
        #pragma unroll 8
        for (int h = 0; h < HDIM; ++h) s += bu[h] * wd[i * HDIM + h];
        sc.c[i] = s;
        sc.bd[i] = bd[i];
    }
    for (int idx = tid; idx < LSTEPS * 16; idx += 256)
        sc.prog[idx >> 4][idx & 15] = prog[idx];
    if (tid < 128) sc.bu64[tid] = 64.f * bu[tid];
    // wd B-frags (k permuted): b0 = wd[i][K+4tg .. +1], b1 = wd[i][K+4tg+2 .. +3]
    for (int idx = tid; idx < 1024; idx += 256) {
        int kc = idx >> 7, cf = (idx >> 6) & 1, hl = (idx >> 5) & 1, ln = idx & 31;
        int gg = ln >> 2, tt = ln & 3;
        const float* p = wd + (cf * 8 + gg) * HDIM + kc * 16 + 4 * tt;
        sc.wdf[kc][cf][hl][ln] = mk_bfrag(p[0], p[1], p[2], p[3], hl);
    }
    // wu B-frags (n permuted): h = s*16 + 2*g + grp ; k = j natural
    for (int idx = tid; idx < 1024; idx += 256) {
        int s_ = idx >> 7, grp = (idx >> 6) & 1, hl = (idx >> 5) & 1, ln = idx & 31;
        int gg = ln >> 2, tt = ln & 3;
        const float* p = wu + (s_ * 16 + 2 * gg + grp) * 16;
        sc.wuf[s_][grp][hl][ln] =
            mk_bfrag(p[2 * tt], p[2 * tt + 1], p[2 * tt + 8], p[2 * tt + 9], hl);
    }
    __syncthreads();

    int lane = tid & 31, wrp = tid >> 5;
    int g = lane >> 2, tg = lane & 3;
    int cbl = 2 * tg;
    long row0 = (long)blockIdx.x * 256 + wrp * 32;
    const float* xw = x + row0 * HDIM;
    float* ow = out + row0 * HDIM;

    // ---- phase A: zf = bd ; zf += x@wd.T (float4 gmem, permuted k) ----
    float zf[2][2][4], Rf[2][2][4];
    #pragma unroll
    for (int tl = 0; tl < 2; ++tl)
        #pragma unroll
        for (int cf = 0; cf < 2; ++cf) {
            float b0 = sc.bd[cf * 8 + cbl], b1 = sc.bd[cf * 8 + cbl + 1];
            zf[tl][cf][0] = b0; zf[tl][cf][1] = b1;
            zf[tl][cf][2] = b0; zf[tl][cf][3] = b1;
            Rf[tl][cf][0] = Rf[tl][cf][1] = Rf[tl][cf][2] = Rf[tl][cf][3] = 0.f;
        }

    #pragma unroll 1
    for (int kc = 0; kc < 8; ++kc) {
        uint32_t wh0[2], wl0[2], wh1[2], wl1[2];
        split_u64(sc.wdf[kc][0][0][lane], wh0);
        split_u64(sc.wdf[kc][0][1][lane], wl0);
        split_u64(sc.wdf[kc][1][0][lane], wh1);
        split_u64(sc.wdf[kc][1][1][lane], wl1);
        #pragma unroll
        for (int tl = 0; tl < 2; ++tl) {
            const float* xp = xw + (long)(tl * 16 + g) * HDIM + kc * 16 + 4 * tg;
            float4 u = *(const float4*)xp;
            float4 w = *(const float4*)(xp + 8 * HDIM);
            uint32_t ah[4], al[4];
            ah[0] = pkbf(u.x, u.y); ah[1] = pkbf(w.x, w.y);
            ah[2] = pkbf(u.z, u.w); ah[3] = pkbf(w.z, w.w);
            al[0] = pkbf(u.x - bhi_f(u.x), u.y - bhi_f(u.y));
            al[1] = pkbf(w.x - bhi_f(w.x), w.y - bhi_f(w.y));
            al[2] = pkbf(u.z - bhi_f(u.z), u.w - bhi_f(u.w));
            al[3] = pkbf(w.z - bhi_f(w.z), w.w - bhi_f(w.w));
            mma_bf16(zf[tl][0], ah, wh0);
            mma_bf16(zf[tl][0], al, wh0);
            mma_bf16(zf[tl][0], ah, wl0);
            mma_bf16(zf[tl][1], ah, wh1);
            mma_bf16(zf[tl][1], al, wh1);
            mma_bf16(zf[tl][1], ah, wl1);
        }
    }

    // ---- phase B fragments of A (bf16-hi) + identity ----
    uint32_t bh[2][2], bI[2][2];
    {
        int k0 = cbl;
        #pragma unroll
        for (int nc = 0; nc < 2; ++nc) {
            int n = g + nc * 8;
            bh[nc][0] = pkbf(sc.A[k0][n],     sc.A[k0 + 1][n]);
            bh[nc][1] = pkbf(sc.A[k0 + 8][n], sc.A[k0 + 9][n]);
            int j = nc * 8 + g;
            bI[nc][0] = pkbf((k0 == j) ? 1.f : 0.f, (k0 + 1 == j) ? 1.f : 0.f);
            bI[nc][1] = pkbf((k0 + 8 == j) ? 1.f : 0.f, (k0 + 9 == j) ? 1.f : 0.f);
        }
    }
    float cc[2][2] = {{sc.c[cbl], sc.c[cbl + 1]},
                      {sc.c[8 + cbl], sc.c[8 + cbl + 1]}};

    // ---- phase B: 64 steps; z += mh@Ah ; R += mh@I ----
    #pragma unroll 1
    for (int t = 0; t < LSTEPS; ++t) {
        float tf = (float)t;
        float zc0 = cc[0][0] * tf, zc1 = cc[0][1] * tf;
        float zc2 = cc[1][0] * tf, zc3 = cc[1][1] * tf;
        float2 pa = *(const float2*)&sc.prog[t][cbl];
        float2 pb = *(const float2*)&sc.prog[t][8 + cbl];

        #pragma unroll
        for (int tl = 0; tl < 2; ++tl) {
            float m00 = fmaxf(zf[tl][0][0] + zc0, 0.f) * pa.x;
            float m01 = fmaxf(zf[tl][0][1] + zc1, 0.f) * pa.y;
            float m02 = fmaxf(zf[tl][0][2] + zc0, 0.f) * pa.x;
            float m03 = fmaxf(zf[tl][0][3] + zc1, 0.f) * pa.y;
            float m10 = fmaxf(zf[tl][1][0] + zc2, 0.f) * pb.x;
            float m11 = fmaxf(zf[tl][1][1] + zc3, 0.f) * pb.y;
            float m12 = fmaxf(zf[tl][1][2] + zc2, 0.f) * pb.x;
            float m13 = fmaxf(zf[tl][1][3] + zc3, 0.f) * pb.y;
            uint32_t ah[4];
            ah[0] = pkbf(m00, m01);
            ah[1] = pkbf(m02, m03);
            ah[2] = pkbf(m10, m11);
            ah[3] = pkbf(m12, m13);
            mma_bf16(zf[tl][0], ah, bh[0]);
            mma_bf16(zf[tl][1], ah, bh[1]);
            mma_bf16(Rf[tl][0], ah, bI[0]);
            mma_bf16(Rf[tl][1], ah, bI[1]);
        }
    }

    // ---- phase C: out = x + R@wu.T + 64*bu (permuted n, float4 I/O) ----
    #pragma unroll
    for (int tl = 0; tl < 2; ++tl) {
        uint32_t rh[4], rl[4];
        rh[0] = pkbf(Rf[tl][0][0], Rf[tl][0][1]);
        rh[1] = pkbf(Rf[tl][0][2], Rf[tl][0][3]);
        rh[2] = pkbf(Rf[tl][1][0], Rf[tl][1][1]);
        rh[3] = pkbf(Rf[tl][1][2], Rf[tl][1][3]);
        rl[0] = pkbf(Rf[tl][0][0] - bhi_f(Rf[tl][0][0]),
                     Rf[tl][0][1] - bhi_f(Rf[tl][0][1]));
        rl[1] = pkbf(Rf[tl][0][2] - bhi_f(Rf[tl][0][2]),
                     Rf[tl][0][3] - bhi_f(Rf[tl][0][3]));
        rl[2] = pkbf(Rf[tl][1][0] - bhi_f(Rf[tl][1][0]),
                     Rf[tl][1][1] - bhi_f(Rf[tl][1][1]));
        rl[3] = pkbf(Rf[tl][1][2] - bhi_f(Rf[tl][1][2]),
                     Rf[tl][1][3] - bhi_f(Rf[tl][1][3]));

        #pragma unroll 1
        for (int s = 0; s < 8; ++s) {
            const float* xp0 = xw + (long)(tl * 16 + g) * HDIM + s * 16 + 4 * tg;
            const float* xp1 = xp0 + 8 * HDIM;
            float4 xv0 = *(const float4*)xp0;
            float4 xv1 = *(const float4*)xp1;
            float4 b = *(const float4*)&sc.bu64[s * 16 + 4 * tg];
            // grp0 frag cols h = s*16 + {4tg, 4tg+2}; grp1: {4tg+1, 4tg+3}
            float o0[4] = {xv0.x + b.x, xv0.z + b.z, xv1.x + b.x, xv1.z + b.z};
            float o1[4] = {xv0.y + b.y, xv0.w + b.w, xv1.y + b.y, xv1.w + b.w};
            uint32_t w0h[2], w0l[2], w1h[2], w1l[2];
            split_u64(sc.wuf[s][0][0][lane], w0h);
            split_u64(sc.wuf[s][0][1][lane], w0l);
            split_u64(sc.wuf[s][1][0][lane], w1h);
            split_u64(sc.wuf[s][1][1][lane], w1l);
            mma_bf16(o0, rh, w0h);
            mma_bf16(o0, rl, w0h);
            mma_bf16(o0, rh, w0l);
            mma_bf16(o1, rh, w1h);
            mma_bf16(o1, rl, w1h);
            mma_bf16(o1, rh, w1l);
            float* op0 = ow + (long)(tl * 16 + g) * HDIM + s * 16 + 4 * tg;
            *(float4*)op0              = make_float4(o0[0], o1[0], o0[1], o1[1]);
            *(float4*)(op0 + 8 * HDIM) = make_float4(o0[2], o1[2], o0[3], o1[3]);
        }
    }
}

extern "C" void kernel_launch(void* const* d_in, const int* in_sizes, int n_in,
                              void* d_out, int out_size) {
    const float* x    = (const float*)d_in[0];
    const float* prog = (const float*)d_in[1];
    const float* wd   = (const float*)d_in[2];
    const float* bd   = (const float*)d_in[3];
    const float* wu   = (const float*)d_in[4];
    const float* bu   = (const float*)d_in[5];
    float* out = (float*)d_out;

    int rows = in_sizes[0] / HDIM;          // 262144
    int blocks = rows / 256;                // 1024
    proc_kernel<<<blocks, 256>>>(x, out, prog, wd, bd, wu, bu);
}

// round 16
// speedup vs baseline: 1.4754x; 1.4754x over previous
#include <cuda_runtime.h>
#include <cuda_bf16.h>
#include <cstdint>

// ProcessorNet, fully tensor-core resident:
//   z_0 = x@wd.T + bd            (MMA: x hi/lo via float4 LDG, permuted k)
//   m_t = relu(z_t + t*c)*prog_t ; R += m_t (I-MMA) ; z += m_t@A (MMA, A-hi)
//   out = x + R@wu.T + 64*bu     (MMA: R hi/lo, permuted n -> float4 LDG/STG)
// Fast 1-block setup kernel (smem-staged dot products) builds all fragments;
// proc_kernel copies the 22KB const block to smem and never touches gmem
// except coalesced float4 x/out traffic.

#define HDIM 128
#define LSTEPS 64

typedef unsigned long long u64;

struct alignas(16) SC {
    float A[16][16];            // A[j][i] = (wu.T@wd.T)[j][i]
    float prog[LSTEPS][16];
    float bd[16];
    float c[16];                // bu @ wd.T
    float bu64[128];            // 64*bu
    u64 wdf[8][2][2][32];       // [kc][cf][hi/lo][lane] wd B-frags (perm k)
    u64 wuf[8][2][2][32];       // [s][grp][hi/lo][lane]  wu B-frags (perm n)
};
__device__ SC g_sc;
#define SC_FLOAT4 (sizeof(SC) / 16)

__device__ __forceinline__ float bhi_f(float v) {
    return __bfloat162float(__float2bfloat16(v));
}
__device__ __forceinline__ uint32_t pkbf(float a, float b) {   // low=a, high=b
    __nv_bfloat162 h = __floats2bfloat162_rn(a, b);
    return *reinterpret_cast<uint32_t*>(&h);
}
__device__ __forceinline__ u64 mk_bfrag(float v0, float v1, float v2, float v3,
                                        int hl) {
    if (hl) {
        v0 -= bhi_f(v0); v1 -= bhi_f(v1);
        v2 -= bhi_f(v2); v3 -= bhi_f(v3);
    }
    return ((u64)pkbf(v2, v3) << 32) | pkbf(v0, v1);
}
__device__ __forceinline__ void split_u64(u64 v, uint32_t* b) {
    b[0] = (uint32_t)v; b[1] = (uint32_t)(v >> 32);
}
__device__ __forceinline__ void mma_bf16(float* d, const uint32_t* a,
                                         const uint32_t* b) {
    asm volatile(
        "mma.sync.aligned.m16n8k16.row.col.f32.bf16.bf16.f32 "
        "{%0,%1,%2,%3}, {%4,%5,%6,%7}, {%8,%9}, {%0,%1,%2,%3};\n"
        : "+f"(d[0]), "+f"(d[1]), "+f"(d[2]), "+f"(d[3])
        : "r"(a[0]), "r"(a[1]), "r"(a[2]), "r"(a[3]), "r"(b[0]), "r"(b[1]));
}

// ---- fast setup: 1 block, 1024 threads, smem-staged dot products ----
__global__ __launch_bounds__(1024)
void setup_kernel(const float* __restrict__ prog, const float* __restrict__ wd,
                  const float* __restrict__ bd, const float* __restrict__ wu,
                  const float* __restrict__ bu) {
    __shared__ float swd[16][129];   // wd[i][h], padded
    __shared__ float swu[128][17];   // wu[h][j], padded
    int tid = threadIdx.x;

    for (int idx = tid; idx < 2048; idx += 1024)
        swd[idx >> 7][idx & 127] = wd[idx];
    for (int idx = tid; idx < 2048; idx += 1024)
        swu[idx >> 4][idx & 15] = wu[idx];
    __syncthreads();

    if (tid < 256) {   // A[j][i] = sum_h wu[h][j]*wd[i][h]
        int j = tid >> 4, i = tid & 15;
        float s = 0.f;
        #pragma unroll 8
        for (int h = 0; h < HDIM; ++h) s += swu[h][j] * swd[i][h];
        g_sc.A[j][i] = s;
    } else if (tid < 272) {   // c[i] = sum_h bu[h]*wd[i][h]
        int i = tid - 256;
        float s = 0.f;
        #pragma unroll 8
        for (int h = 0; h < HDIM; ++h) s += bu[h] * swd[i][h];
        g_sc.c[i] = s;
        g_sc.bd[i] = bd[i];
    }
    if (tid < LSTEPS * 16) g_sc.prog[tid >> 4][tid & 15] = prog[tid];
    if (tid < 128) g_sc.bu64[tid] = 64.f * bu[tid];

    // wd B-frags (k permuted): values wd[i][kc*16 + 4tg .. +3]
    {
        int idx = tid;   // 1024 exactly
        int kc = idx >> 7, cf = (idx >> 6) & 1, hl = (idx >> 5) & 1, ln = idx & 31;
        int gg = ln >> 2, tt = ln & 3;
        const float* p = &swd[cf * 8 + gg][kc * 16 + 4 * tt];
        g_sc.wdf[kc][cf][hl][ln] = mk_bfrag(p[0], p[1], p[2], p[3], hl);
    }
    // wu B-frags (n permuted): h = s*16 + 2*g + grp ; k = j natural
    {
        int idx = tid;
        int s_ = idx >> 7, grp = (idx >> 6) & 1, hl = (idx >> 5) & 1, ln = idx & 31;
        int gg = ln >> 2, tt = ln & 3;
        const float* p = &swu[s_ * 16 + 2 * gg + grp][0];
        g_sc.wuf[s_][grp][hl][ln] =
            mk_bfrag(p[2 * tt], p[2 * tt + 1], p[2 * tt + 8], p[2 * tt + 9], hl);
    }
}

__global__ __launch_bounds__(256, 4)
void proc_kernel(const float* __restrict__ x, float* __restrict__ out) {
    __shared__ SC sc;
    int tid = threadIdx.x;
    {
        const float4* src = (const float4*)&g_sc;
        float4* dst = (float4*)&sc;
        for (int i = tid; i < (int)SC_FLOAT4; i += 256) dst[i] = src[i];
    }
    __syncthreads();

    int lane = tid & 31, wrp = tid >> 5;
    int g = lane >> 2, tg = lane & 3;
    int cbl = 2 * tg;
    long row0 = (long)blockIdx.x * 256 + wrp * 32;
    const float* xw = x + row0 * HDIM;
    float* ow = out + row0 * HDIM;

    // ---- phase A: zf = bd ; zf += x@wd.T (float4 gmem, permuted k) ----
    float zf[2][2][4], Rf[2][2][4];
    #pragma unroll
    for (int tl = 0; tl < 2; ++tl)
        #pragma unroll
        for (int cf = 0; cf < 2; ++cf) {
            float b0 = sc.bd[cf * 8 + cbl], b1 = sc.bd[cf * 8 + cbl + 1];
            zf[tl][cf][0] = b0; zf[tl][cf][1] = b1;
            zf[tl][cf][2] = b0; zf[tl][cf][3] = b1;
            Rf[tl][cf][0] = Rf[tl][cf][1] = Rf[tl][cf][2] = Rf[tl][cf][3] = 0.f;
        }

    #pragma unroll 1
    for (int kc = 0; kc < 8; ++kc) {
        uint32_t wh0[2], wl0[2], wh1[2], wl1[2];
        split_u64(sc.wdf[kc][0][0][lane], wh0);
        split_u64(sc.wdf[kc][0][1][lane], wl0);
        split_u64(sc.wdf[kc][1][0][lane], wh1);
        split_u64(sc.wdf[kc][1][1][lane], wl1);
        #pragma unroll
        for (int tl = 0; tl < 2; ++tl) {
            const float* xp = xw + (long)(tl * 16 + g) * HDIM + kc * 16 + 4 * tg;
            float4 u = *(const float4*)xp;
            float4 w = *(const float4*)(xp + 8 * HDIM);
            uint32_t ah[4], al[4];
            ah[0] = pkbf(u.x, u.y); ah[1] = pkbf(w.x, w.y);
            ah[2] = pkbf(u.z, u.w); ah[3] = pkbf(w.z, w.w);
            al[0] = pkbf(u.x - bhi_f(u.x), u.y - bhi_f(u.y));
            al[1] = pkbf(w.x - bhi_f(w.x), w.y - bhi_f(w.y));
            al[2] = pkbf(u.z - bhi_f(u.z), u.w - bhi_f(u.w));
            al[3] = pkbf(w.z - bhi_f(w.z), w.w - bhi_f(w.w));
            mma_bf16(zf[tl][0], ah, wh0);
            mma_bf16(zf[tl][0], al, wh0);
            mma_bf16(zf[tl][0], ah, wl0);
            mma_bf16(zf[tl][1], ah, wh1);
            mma_bf16(zf[tl][1], al, wh1);
            mma_bf16(zf[tl][1], ah, wl1);
        }
    }

    // ---- phase B fragments of A (bf16-hi) + identity ----
    uint32_t bh[2][2], bI[2][2];
    {
        int k0 = cbl;
        #pragma unroll
        for (int nc = 0; nc < 2; ++nc) {
            int n = g + nc * 8;
            bh[nc][0] = pkbf(sc.A[k0][n],     sc.A[k0 + 1][n]);
            bh[nc][1] = pkbf(sc.A[k0 + 8][n], sc.A[k0 + 9][n]);
            int j = nc * 8 + g;
            bI[nc][0] = pkbf((k0 == j) ? 1.f : 0.f, (k0 + 1 == j) ? 1.f : 0.f);
            bI[nc][1] = pkbf((k0 + 8 == j) ? 1.f : 0.f, (k0 + 9 == j) ? 1.f : 0.f);
        }
    }
    float cc[2][2] = {{sc.c[cbl], sc.c[cbl + 1]},
                      {sc.c[8 + cbl], sc.c[8 + cbl + 1]}};

    // ---- phase B: 64 steps; z += mh@Ah ; R += mh@I ----
    #pragma unroll 1
    for (int t = 0; t < LSTEPS; ++t) {
        float tf = (float)t;
        float zc0 = cc[0][0] * tf, zc1 = cc[0][1] * tf;
        float zc2 = cc[1][0] * tf, zc3 = cc[1][1] * tf;
        float2 pa = *(const float2*)&sc.prog[t][cbl];
        float2 pb = *(const float2*)&sc.prog[t][8 + cbl];

        #pragma unroll
        for (int tl = 0; tl < 2; ++tl) {
            float m00 = fmaxf(zf[tl][0][0] + zc0, 0.f) * pa.x;
            float m01 = fmaxf(zf[tl][0][1] + zc1, 0.f) * pa.y;
            float m02 = fmaxf(zf[tl][0][2] + zc0, 0.f) * pa.x;
            float m03 = fmaxf(zf[tl][0][3] + zc1, 0.f) * pa.y;
            float m10 = fmaxf(zf[tl][1][0] + zc2, 0.f) * pb.x;
            float m11 = fmaxf(zf[tl][1][1] + zc3, 0.f) * pb.y;
            float m12 = fmaxf(zf[tl][1][2] + zc2, 0.f) * pb.x;
            float m13 = fmaxf(zf[tl][1][3] + zc3, 0.f) * pb.y;
            uint32_t ah[4];
            ah[0] = pkbf(m00, m01);
            ah[1] = pkbf(m02, m03);
            ah[2] = pkbf(m10, m11);
            ah[3] = pkbf(m12, m13);
            mma_bf16(zf[tl][0], ah, bh[0]);
            mma_bf16(zf[tl][1], ah, bh[1]);
            mma_bf16(Rf[tl][0], ah, bI[0]);
            mma_bf16(Rf[tl][1], ah, bI[1]);
        }
    }

    // ---- phase C: out = x + R@wu.T + 64*bu (permuted n, float4 I/O) ----
    #pragma unroll
    for (int tl = 0; tl < 2; ++tl) {
        uint32_t rh[4], rl[4];
        rh[0] = pkbf(Rf[tl][0][0], Rf[tl][0][1]);
        rh[1] = pkbf(Rf[tl][0][2], Rf[tl][0][3]);
        rh[2] = pkbf(Rf[tl][1][0], Rf[tl][1][1]);
        rh[3] = pkbf(Rf[tl][1][2], Rf[tl][1][3]);
        rl[0] = pkbf(Rf[tl][0][0] - bhi_f(Rf[tl][0][0]),
                     Rf[tl][0][1] - bhi_f(Rf[tl][0][1]));
        rl[1] = pkbf(Rf[tl][0][2] - bhi_f(Rf[tl][0][2]),
                     Rf[tl][0][3] - bhi_f(Rf[tl][0][3]));
        rl[2] = pkbf(Rf[tl][1][0] - bhi_f(Rf[tl][1][0]),
                     Rf[tl][1][1] - bhi_f(Rf[tl][1][1]));
        rl[3] = pkbf(Rf[tl][1][2] - bhi_f(Rf[tl][1][2]),
                     Rf[tl][1][3] - bhi_f(Rf[tl][1][3]));

        #pragma unroll 1
        for (int s = 0; s < 8; ++s) {
            const float* xp0 = xw + (long)(tl * 16 + g) * HDIM + s * 16 + 4 * tg;
            const float* xp1 = xp0 + 8 * HDIM;
            float4 xv0 = *(const float4*)xp0;
            float4 xv1 = *(const float4*)xp1;
            float4 b = *(const float4*)&sc.bu64[s * 16 + 4 * tg];
            // grp0 frag cols h = s*16 + {4tg, 4tg+2}; grp1: {4tg+1, 4tg+3}
            float o0[4] = {xv0.x + b.x, xv0.z + b.z, xv1.x + b.x, xv1.z + b.z};
            float o1[4] = {xv0.y + b.y, xv0.w + b.w, xv1.y + b.y, xv1.w + b.w};
            uint32_t w0h[2], w0l[2], w1h[2], w1l[2];
            split_u64(sc.wuf[s][0][0][lane], w0h);
            split_u64(sc.wuf[s][0][1][lane], w0l);
            split_u64(sc.wuf[s][1][0][lane], w1h);
            split_u64(sc.wuf[s][1][1][lane], w1l);
            mma_bf16(o0, rh, w0h);
            mma_bf16(o0, rl, w0h);
            mma_bf16(o0, rh, w0l);
            mma_bf16(o1, rh, w1h);
            mma_bf16(o1, rl, w1h);
            mma_bf16(o1, rh, w1l);
            float* op0 = ow + (long)(tl * 16 + g) * HDIM + s * 16 + 4 * tg;
            *(float4*)op0              = make_float4(o0[0], o1[0], o0[1], o1[1]);
            *(float4*)(op0 + 8 * HDIM) = make_float4(o0[2], o1[2], o0[3], o1[3]);
        }
    }
}

extern "C" void kernel_launch(void* const* d_in, const int* in_sizes, int n_in,
                              void* d_out, int out_size) {
    const float* x    = (const float*)d_in[0];
    const float* prog = (const float*)d_in[1];
    const float* wd   = (const float*)d_in[2];
    const float* bd   = (const float*)d_in[3];
    const float* wu   = (const float*)d_in[4];
    const float* bu   = (const float*)d_in[5];
    float* out = (float*)d_out;

    setup_kernel<<<1, 1024>>>(prog, wd, bd, wu, bu);

    int rows = in_sizes[0] / HDIM;          // 262144
    int blocks = rows / 256;                // 1024
    proc_kernel<<<blocks, 256>>>(x, out);
}